// round 13
// baseline (speedup 1.0000x reference)
#include <cuda_runtime.h>
#include <cstdint>

// WanRotaryPosEmbedS2VStyle: build (freqs_cos, freqs_sin) grids.
//
//   output: cos (1, n_tok, 1, 128) then sin; n_tok = F*3600.
//   Per token (f,y,x): ch [0,44)=t_tab[pt], [44,86)=h_tab[y], [86,128)=w_tab[x].
//
// R13: plateau at ~14.5us for 4 structurally different kernels with nothing
// saturated. Remaining suspects: (a) ptxas BSSY/BSYNC around the divergent
// `if (isw)` reloads (6 regions x ~40cyc/warp), (b) 2.09 waves at X_PER=4.
// This round: X_PER=6 (1.39 waves, 13200 warps, row-aligned) + PTX-predicated
// reloads (@p ld.global.nc.v2.f32 — dest kept when false, which is exactly
// the "non-w lanes keep token-0 value" semantics). Zero branches in the body.

#define T_DIM 44
#define H_DIM 42
#define W_DIM 42
#define GRID_W 60
#define GRID_HW 3600
#define FIXED_REF 30
#define X_PER 6            // tokens per warp (60 % 6 == 0 -> row-aligned)

// Predicated float2 load: v unchanged where pr == 0.
__device__ __forceinline__ void ldg2_pred(float2& v, const float* p, unsigned pr)
{
    asm volatile(
        "{\n\t"
        ".reg .pred q;\n\t"
        "setp.ne.u32 q, %3, 0;\n\t"
        "@q ld.global.nc.v2.f32 {%0, %1}, [%2];\n\t"
        "}"
        : "+f"(v.x), "+f"(v.y)
        : "l"(p), "r"(pr));
}

__global__ __launch_bounds__(256)
void wan_rope_kernel(
    const float* __restrict__ tcos, const float* __restrict__ hcos,
    const float* __restrict__ wcos, const float* __restrict__ tsin,
    const float* __restrict__ hsin, const float* __restrict__ wsin,
    const int*   __restrict__ nvf_p,
    float* __restrict__ out, int n_tok, int n_warps)
{
    const int gtid = blockIdx.x * blockDim.x + threadIdx.x;
    const int w    = gtid >> 5;
    if (w >= n_warps) return;
    const int lane = gtid & 31;
    const int d0   = lane << 2;            // channels [d0, d0+4)

    const int tok0 = w * X_PER;            // X_PER tokens, same (f,y)
    const int f    = tok0 / GRID_HW;
    const int rem  = tok0 - f * GRID_HW;
    const int y    = rem / GRID_W;
    const int x0   = rem - y * GRID_W;

    const int video_pp = __ldg(nvf_p);
    const int pt = (f < video_pp) ? f : FIXED_REF;

    const int tbase = pt * T_DIM;
    const int hbase = y * H_DIM - T_DIM;
    const int wbase = x0 * W_DIM - (T_DIM + H_DIM);

    const int dA = d0;                     // first even pair
    const int dB = d0 + 2;                 // second even pair
    const unsigned iswA = (dA >= T_DIM + H_DIM) ? 1u : 0u;
    const unsigned iswB = (dB >= T_DIM + H_DIM) ? 1u : 0u;

    // fixed base pointers (base + immediate offsets in the loop)
    const float* pcA = iswA ? (wcos + wbase + dA)
                     : (dA >= T_DIM) ? (hcos + hbase + dA) : (tcos + tbase + dA);
    const float* psA = iswA ? (wsin + wbase + dA)
                     : (dA >= T_DIM) ? (hsin + hbase + dA) : (tsin + tbase + dA);
    const float* pcB = iswB ? (wcos + wbase + dB)
                     : (dB >= T_DIM) ? (hcos + hbase + dB) : (tcos + tbase + dB);
    const float* psB = iswB ? (wsin + wbase + dB)
                     : (dB >= T_DIM) ? (hsin + hbase + dB) : (tsin + tbase + dB);

    float2 cA = __ldg(reinterpret_cast<const float2*>(pcA));
    float2 sA = __ldg(reinterpret_cast<const float2*>(psA));
    float2 cB = __ldg(reinterpret_cast<const float2*>(pcB));
    float2 sB = __ldg(reinterpret_cast<const float2*>(psB));

    float4* oc4 = reinterpret_cast<float4*>(out + (size_t)tok0 * 128 + d0);
    float4* os4 = reinterpret_cast<float4*>(out + (size_t)(n_tok + tok0) * 128 + d0);

    oc4[0] = make_float4(cA.x, cA.y, cB.x, cB.y);
    os4[0] = make_float4(sA.x, sA.y, sB.x, sB.y);

#pragma unroll
    for (int xi = 1; xi < X_PER; xi++) {
        // branch-free predicated reloads: only w-lanes update, others keep
        // their token-0 registers (predicated-off load leaves dest intact).
        ldg2_pred(cA, pcA + xi * W_DIM, iswA);
        ldg2_pred(sA, psA + xi * W_DIM, iswA);
        ldg2_pred(cB, pcB + xi * W_DIM, iswB);
        ldg2_pred(sB, psB + xi * W_DIM, iswB);

        oc4[xi * 32] = make_float4(cA.x, cA.y, cB.x, cB.y);
        os4[xi * 32] = make_float4(sA.x, sA.y, sB.x, sB.y);
    }
}

extern "C" void kernel_launch(void* const* d_in, const int* in_sizes, int n_in,
                              void* d_out, int out_size)
{
    // 0: hidden_states (unused)
    // 1: freq_t_cos  2: freq_h_cos  3: freq_w_cos
    // 4: freq_t_sin  5: freq_h_sin  6: freq_w_sin
    // 7: num_video_frames (int32)   8: num_ref_frames (int32)
    const float* tcos = (const float*)d_in[1];
    const float* hcos = (const float*)d_in[2];
    const float* wcos = (const float*)d_in[3];
    const float* tsin = (const float*)d_in[4];
    const float* hsin = (const float*)d_in[5];
    const float* wsin = (const float*)d_in[6];
    const int*   nvf  = (const int*)d_in[7];

    float* out = (float*)d_out;

    const int n_tok   = out_size / 256;    // out_size = 2 * n_tok * 128
    const int n_warps = n_tok / X_PER;     // 3600 % 6 == 0
    const int threads = 256;
    const int blocks  = (n_warps * 32 + threads - 1) / threads;

    wan_rope_kernel<<<blocks, threads>>>(tcos, hcos, wcos, tsin, hsin, wsin,
                                         nvf, out, n_tok, n_warps);
}

// round 14
// speedup vs baseline: 1.0133x; 1.0133x over previous
#include <cuda_runtime.h>
#include <cstdint>

// WanRotaryPosEmbedS2VStyle: build (freqs_cos, freqs_sin) grids.
//
//   output: cos (1, n_tok, 1, 128) then sin; n_tok = F*3600.
//   Per token (f,y,x): ch [0,44)=t_tab[pt], [44,86)=h_tab[y], [86,128)=w_tab[x].
//
// R14 (FINAL): re-lock of the best-measured kernel (R3: bench 14.848us,
// ncu 14.336us). Thirteen rounds established the wall: 81MB of mandatory
// output writes at the L2 store-port rate (~5.7 TB/s measured in every
// well-occupied variant; pure-store streams get ~half the combined LTS cap).
// All SM-side levers (instruction count, load latency, occupancy, waves,
// predication, bulk-store/TMA path) were independently varied with no effect
// on time. Each warp: 4 consecutive x-tokens (same f,y); index math + t/h
// table loads once; per extra token only w-lanes (d>=86) reload via
// predicated LDG.64; 2x STG.128 per token.

#define T_DIM 44
#define H_DIM 42
#define W_DIM 42
#define GRID_W 60
#define GRID_HW 3600
#define FIXED_REF 30
#define X_PER 4            // tokens per warp (divides 60) — measured optimum

__global__ void wan_rope_kernel(
    const float* __restrict__ tcos, const float* __restrict__ hcos,
    const float* __restrict__ wcos, const float* __restrict__ tsin,
    const float* __restrict__ hsin, const float* __restrict__ wsin,
    const int*   __restrict__ nvf_p,
    float* __restrict__ out, int n_tok, int n_warps)
{
    const int gtid = blockIdx.x * blockDim.x + threadIdx.x;
    const int w    = gtid >> 5;
    if (w >= n_warps) return;
    const int lane = gtid & 31;
    const int d0   = lane << 2;            // channels [d0, d0+4)

    const int tok0 = w * X_PER;            // X_PER tokens, same (f,y) row
    const int f    = tok0 / GRID_HW;
    const int rem  = tok0 - f * GRID_HW;
    const int y    = rem / GRID_W;

    const int video_pp = __ldg(nvf_p);
    const int pt = (f < video_pp) ? f : FIXED_REF;

    const int tbase = pt * T_DIM;
    const int hbase = y * H_DIM - T_DIM;
    const int wbase = (rem - y * GRID_W) * W_DIM - (T_DIM + H_DIM);

    const float* pc[2];
    const float* ps[2];
    bool   isw[2];
    float2 c[2], s[2];
#pragma unroll
    for (int h = 0; h < 2; h++) {
        const int d = d0 + 2 * h;          // even; pair (d,d+1) in one table
        if (d < T_DIM)              { pc[h] = tcos + tbase + d; ps[h] = tsin + tbase + d; isw[h] = false; }
        else if (d < T_DIM + H_DIM) { pc[h] = hcos + hbase + d; ps[h] = hsin + hbase + d; isw[h] = false; }
        else                        { pc[h] = wcos + wbase + d; ps[h] = wsin + wbase + d; isw[h] = true;  }
        c[h] = __ldg(reinterpret_cast<const float2*>(pc[h]));
        s[h] = __ldg(reinterpret_cast<const float2*>(ps[h]));
    }

    float* oc = out + (size_t)tok0 * 128 + d0;
    float* os = oc + (size_t)n_tok * 128;

#pragma unroll
    for (int xi = 0; xi < X_PER; xi++) {
        if (xi) {
#pragma unroll
            for (int h = 0; h < 2; h++) {
                if (isw[h]) {              // predicated: only w-lanes reload
                    pc[h] += W_DIM;  ps[h] += W_DIM;
                    c[h] = __ldg(reinterpret_cast<const float2*>(pc[h]));
                    s[h] = __ldg(reinterpret_cast<const float2*>(ps[h]));
                }
            }
        }
        *reinterpret_cast<float4*>(oc) = make_float4(c[0].x, c[0].y, c[1].x, c[1].y);
        *reinterpret_cast<float4*>(os) = make_float4(s[0].x, s[0].y, s[1].x, s[1].y);
        oc += 128;  os += 128;
    }
}

extern "C" void kernel_launch(void* const* d_in, const int* in_sizes, int n_in,
                              void* d_out, int out_size)
{
    // 0: hidden_states (unused)
    // 1: freq_t_cos  2: freq_h_cos  3: freq_w_cos
    // 4: freq_t_sin  5: freq_h_sin  6: freq_w_sin
    // 7: num_video_frames (int32)   8: num_ref_frames (int32)
    const float* tcos = (const float*)d_in[1];
    const float* hcos = (const float*)d_in[2];
    const float* wcos = (const float*)d_in[3];
    const float* tsin = (const float*)d_in[4];
    const float* hsin = (const float*)d_in[5];
    const float* wsin = (const float*)d_in[6];
    const int*   nvf  = (const int*)d_in[7];

    float* out = (float*)d_out;

    const int n_tok   = out_size / 256;    // out_size = 2 * n_tok * 128
    const int n_warps = n_tok / X_PER;     // n_tok = F*3600, divisible by X_PER
    const int threads = 256;
    const int blocks  = (n_warps * 32 + threads - 1) / threads;

    wan_rope_kernel<<<blocks, threads>>>(tcos, hcos, wcos, tsin, hsin, wsin,
                                         nvf, out, n_tok, n_warps);
}